// round 3
// baseline (speedup 1.0000x reference)
#include <cuda_runtime.h>

#define NQ 10

// cos(weights), computed once per launch by a tiny prep kernel.
__device__ float g_cw[NQ];

__global__ void prep_cw_kernel(const float* __restrict__ w) {
    int i = threadIdx.x;
    if (i < NQ) g_cw[i] = cosf(w[i]);
}

// Each thread processes TWO rows of NQ=10 floats = 80 bytes = 5x float4,
// guaranteeing 16B alignment and fully coalesced 128-bit loads/stores.
__global__ void __launch_bounds__(256)
qcumprod_kernel(const float* __restrict__ x, float* __restrict__ out,
                long long n_pairs) {
    long long t = (long long)blockIdx.x * blockDim.x + threadIdx.x;
    if (t >= n_pairs) return;

    float cw[NQ];
#pragma unroll
    for (int i = 0; i < NQ; i++) cw[i] = g_cw[i];

    const float4* __restrict__ xin = reinterpret_cast<const float4*>(x) + t * 5;
    float e[20];
#pragma unroll
    for (int i = 0; i < 5; i++) {
        float4 v = xin[i];
        e[4 * i + 0] = v.x;
        e[4 * i + 1] = v.y;
        e[4 * i + 2] = v.z;
        e[4 * i + 3] = v.w;
    }

    // Row 0 cumprod
    float p = 1.0f;
#pragma unroll
    for (int i = 0; i < NQ; i++) {
        p *= cosf(e[i]) * cw[i];
        e[i] = p;
    }
    // Row 1 cumprod
    p = 1.0f;
#pragma unroll
    for (int i = 0; i < NQ; i++) {
        p *= cosf(e[NQ + i]) * cw[i];
        e[NQ + i] = p;
    }

    float4* __restrict__ o = reinterpret_cast<float4*>(out) + t * 5;
#pragma unroll
    for (int i = 0; i < 5; i++) {
        o[i] = make_float4(e[4 * i + 0], e[4 * i + 1], e[4 * i + 2], e[4 * i + 3]);
    }
}

// Scalar fallback (one row per thread) in case total elems isn't a multiple of 20.
__global__ void __launch_bounds__(256)
qcumprod_scalar_kernel(const float* __restrict__ x, float* __restrict__ out,
                       long long n_rows) {
    long long t = (long long)blockIdx.x * blockDim.x + threadIdx.x;
    if (t >= n_rows) return;
    float cw[NQ];
#pragma unroll
    for (int i = 0; i < NQ; i++) cw[i] = g_cw[i];
    const float* xr = x + t * NQ;
    float* orow = out + t * NQ;
    float p = 1.0f;
#pragma unroll
    for (int i = 0; i < NQ; i++) {
        p *= cosf(xr[i]) * cw[i];
        orow[i] = p;
    }
}

extern "C" void kernel_launch(void* const* d_in, const int* in_sizes, int n_in,
                              void* d_out, int out_size) {
    // Identify inputs by size: weights has NQ elements, x has the rest.
    const float* x = (const float*)d_in[0];
    const float* w = (const float*)d_in[1];
    long long n = in_sizes[0];
    if (in_sizes[0] == NQ && n_in > 1) {
        w = (const float*)d_in[0];
        x = (const float*)d_in[1];
        n = in_sizes[1];
    }
    float* out = (float*)d_out;

    prep_cw_kernel<<<1, 32>>>(w);

    if (n % 20 == 0) {
        long long n_pairs = n / 20;
        int threads = 256;
        long long blocks = (n_pairs + threads - 1) / threads;
        qcumprod_kernel<<<(unsigned int)blocks, threads>>>(x, out, n_pairs);
    } else {
        long long n_rows = n / NQ;
        int threads = 256;
        long long blocks = (n_rows + threads - 1) / threads;
        qcumprod_scalar_kernel<<<(unsigned int)blocks, threads>>>(x, out, n_rows);
    }
}

// round 8
// speedup vs baseline: 1.0579x; 1.0579x over previous
#include <cuda_runtime.h>

#define NQ  10
#define TPB 256
#define RPB 512                 // rows per block
#define FPB (RPB * NQ)          // 5120 floats = 20480 B smem
#define V4PB (FPB / 4)          // 1280 float4 per block (= 5 per thread)

// Main kernel: stages 512 rows through shared memory.
// Load: 5x coalesced float4 per thread. Compute: stream cumprod through smem
// (no register arrays). Store: 5x coalesced float4 per thread.
__global__ void __launch_bounds__(TPB)
qcumprod_smem_kernel(const float4* __restrict__ x4, float4* __restrict__ o4,
                     const float* __restrict__ w) {
    __shared__ float s[FPB];
    __shared__ float s_cwp[NQ];

    const int t = threadIdx.x;
    const long long b4 = (long long)blockIdx.x * V4PB;

    // One thread builds the cumulative cos(w) product while loads fly.
    if (t == 0) {
        float p = 1.0f;
#pragma unroll
        for (int i = 0; i < NQ; i++) { p *= cosf(w[i]); s_cwp[i] = p; }
    }

    // Coalesced global -> smem (conflict-free float4 writes), MLP = 5.
#pragma unroll
    for (int i = 0; i < 5; i++) {
        float4 v = x4[b4 + i * TPB + t];
        reinterpret_cast<float4*>(s)[i * TPB + t] = v;
    }
    __syncthreads();

    // Each thread computes two rows: t and t+256.
    // Row offsets are 10*t mod 32 -> at worst 2-way bank conflicts.
#pragma unroll
    for (int r = 0; r < 2; r++) {
        const int off = (t + r * TPB) * NQ;
        float p = 1.0f;
#pragma unroll
        for (int i = 0; i < NQ; i++) {
            p *= cosf(s[off + i]);
            s[off + i] = p * s_cwp[i];
        }
    }
    __syncthreads();

    // Coalesced smem -> global.
#pragma unroll
    for (int i = 0; i < 5; i++) {
        o4[b4 + i * TPB + t] = reinterpret_cast<const float4*>(s)[i * TPB + t];
    }
}

// Scalar tail kernel for row counts not divisible by RPB.
__global__ void __launch_bounds__(256)
qcumprod_tail_kernel(const float* __restrict__ x, float* __restrict__ out,
                     const float* __restrict__ w,
                     long long row0, long long n_rows) {
    long long r = row0 + (long long)blockIdx.x * blockDim.x + threadIdx.x;
    if (r >= n_rows) return;
    const float* xr = x + r * NQ;
    float* orow = out + r * NQ;
    float p = 1.0f, cp = 1.0f;
#pragma unroll
    for (int i = 0; i < NQ; i++) {
        cp *= cosf(w[i]);
        p  *= cosf(xr[i]);
        orow[i] = p * cp;
    }
}

extern "C" void kernel_launch(void* const* d_in, const int* in_sizes, int n_in,
                              void* d_out, int out_size) {
    // Identify inputs by size: weights has NQ elements, x has the rest.
    const float* x = (const float*)d_in[0];
    const float* w = (const float*)d_in[1];
    long long n = in_sizes[0];
    if (in_sizes[0] == NQ && n_in > 1) {
        w = (const float*)d_in[0];
        x = (const float*)d_in[1];
        n = in_sizes[1];
    }
    float* out = (float*)d_out;

    const long long n_rows = n / NQ;
    const long long nblocks = n_rows / RPB;

    if (nblocks > 0) {
        qcumprod_smem_kernel<<<(unsigned int)nblocks, TPB>>>(
            (const float4*)x, (float4*)out, w);
    }
    const long long done = nblocks * RPB;
    const long long rem = n_rows - done;
    if (rem > 0) {
        int threads = 256;
        long long tb = (rem + threads - 1) / threads;
        qcumprod_tail_kernel<<<(unsigned int)tb, threads>>>(x, out, w, done, n_rows);
    }
}